// round 3
// baseline (speedup 1.0000x reference)
#include <cuda_runtime.h>
#include <math.h>

#define B_  2
#define S_  4096
#define D_  512
#define H_  8
#define HD_ 64
#define BS_ (B_*S_)
#define PAD 68

// Scratch layouts chosen for the attention access pattern:
//   g_q, g_k : [bh][hd][s]  (transposed -> attention loads Qt/Kt tiles coalesced)
//   g_v      : [bh][s][hd]  (natural    -> attention loads V tiles coalesced)
__device__ float g_q[B_*H_*HD_*S_];
__device__ float g_k[B_*H_*HD_*S_];
__device__ float g_v[B_*H_*S_*HD_];

// ---------------------------------------------------------------------------
// Fused QKV projection: y = x @ W^T + b. BM=BN=64, BK=32, 256 thr, 4x4 tile.
// Inner loop: 2x LDS.128 + 16 FMA per k. blockIdx.z selects {Q,K,V}.
// ---------------------------------------------------------------------------
__global__ void __launch_bounds__(256) qkv_gemm(
    const float* __restrict__ x,
    const float* __restrict__ Wq, const float* __restrict__ bq,
    const float* __restrict__ Wk, const float* __restrict__ bk,
    const float* __restrict__ Wv, const float* __restrict__ bv)
{
    __shared__ float As[32][PAD];
    __shared__ float Bs[32][PAD];

    const int z = blockIdx.z;
    const float* W    = (z == 0) ? Wq : ((z == 1) ? Wk : Wv);
    const float* bias = (z == 0) ? bq : ((z == 1) ? bk : bv);
    float* dst        = (z == 0) ? g_q : ((z == 1) ? g_k : g_v);

    const int m0 = blockIdx.y * 64;
    const int n0 = blockIdx.x * 64;
    const int tx = threadIdx.x, ty = threadIdx.y;
    const int t  = ty * 16 + tx;

    float acc[4][4] = {};

    for (int k0 = 0; k0 < D_; k0 += 32) {
        #pragma unroll
        for (int i = 0; i < 2; i++) {
            int f  = t + i * 256;        // 0..511
            int m  = f >> 3;             // 8 float4 per 32-wide row
            int kq = (f & 7) * 4;
            float4 a4 = *(const float4*)(x + (size_t)(m0 + m) * D_ + k0 + kq);
            As[kq + 0][m] = a4.x; As[kq + 1][m] = a4.y;
            As[kq + 2][m] = a4.z; As[kq + 3][m] = a4.w;
            float4 w4 = *(const float4*)(W + (size_t)(n0 + m) * D_ + k0 + kq);
            Bs[kq + 0][m] = w4.x; Bs[kq + 1][m] = w4.y;
            Bs[kq + 2][m] = w4.z; Bs[kq + 3][m] = w4.w;
        }
        __syncthreads();

        #pragma unroll
        for (int k = 0; k < 32; k++) {
            float4 a = *(const float4*)&As[k][4 * ty];
            float4 b = *(const float4*)&Bs[k][4 * tx];
            acc[0][0] = fmaf(a.x, b.x, acc[0][0]); acc[0][1] = fmaf(a.x, b.y, acc[0][1]);
            acc[0][2] = fmaf(a.x, b.z, acc[0][2]); acc[0][3] = fmaf(a.x, b.w, acc[0][3]);
            acc[1][0] = fmaf(a.y, b.x, acc[1][0]); acc[1][1] = fmaf(a.y, b.y, acc[1][1]);
            acc[1][2] = fmaf(a.y, b.z, acc[1][2]); acc[1][3] = fmaf(a.y, b.w, acc[1][3]);
            acc[2][0] = fmaf(a.z, b.x, acc[2][0]); acc[2][1] = fmaf(a.z, b.y, acc[2][1]);
            acc[2][2] = fmaf(a.z, b.z, acc[2][2]); acc[2][3] = fmaf(a.z, b.w, acc[2][3]);
            acc[3][0] = fmaf(a.w, b.x, acc[3][0]); acc[3][1] = fmaf(a.w, b.y, acc[3][1]);
            acc[3][2] = fmaf(a.w, b.z, acc[3][2]); acc[3][3] = fmaf(a.w, b.w, acc[3][3]);
        }
        __syncthreads();
    }

    // Epilogue. row = b*4096 + s ; n = h*64 + hd. 64-row tile never crosses b.
    const int row0 = m0 + 4 * ty;
    const int b    = row0 >> 12;
    const int s0   = row0 & 4095;
    float4 bn4 = *(const float4*)&bias[n0 + 4 * tx];

    if (z < 2) {
        // Transposed layout [bh][hd][s]: float4 along s (i), one store per j.
        const float bn[4] = { bn4.x, bn4.y, bn4.z, bn4.w };
        #pragma unroll
        for (int j = 0; j < 4; j++) {
            int n  = n0 + 4 * tx + j;
            int h  = n >> 6;
            int hd = n & 63;
            float4 o = make_float4(acc[0][j] + bn[j], acc[1][j] + bn[j],
                                   acc[2][j] + bn[j], acc[3][j] + bn[j]);
            *(float4*)&dst[(((size_t)(b * H_ + h)) * HD_ + hd) * S_ + s0] = o;
        }
    } else {
        // Natural layout [bh][s][hd]: float4 along hd (j), coalesced.
        int n  = n0 + 4 * tx;
        int h  = n >> 6;
        int hd = n & 63;
        #pragma unroll
        for (int i = 0; i < 4; i++) {
            float4 o = make_float4(acc[i][0] + bn4.x, acc[i][1] + bn4.y,
                                   acc[i][2] + bn4.z, acc[i][3] + bn4.w);
            *(float4*)&dst[(((size_t)(b * H_ + h)) * S_ + (s0 + i)) * HD_ + hd] = o;
        }
    }
}

// ---------------------------------------------------------------------------
// Causal flash attention. Br=Bc=64, 256 threads (16x16), 4x4 micro-tile.
// All shared traffic is LDS.128 / STS.128, conflict-free or broadcast.
// S-phase per d: 2 LDS.128 + 16 FMA. PV per 4 jj: 8 LDS.128 + 64 FMA.
// ---------------------------------------------------------------------------
__global__ void __launch_bounds__(256, 2) attn_kernel(float* __restrict__ out)
{
    extern __shared__ float sh[];
    float* Qt = sh;                // [64][PAD]  Qt[d][r]   (pre-scaled)
    float* Kt = Qt + 64 * PAD;     // [64][PAD]  Kt[d][c]
    float* Vs = Kt + 64 * PAD;     // [64][PAD]  Vs[jj][hd]
    float* Ps = Vs + 64 * PAD;     // [64][PAD]  Ps[row][jj]

    // Heavy q-tiles first to reduce wave-tail imbalance.
    const int qt = (int)gridDim.x - 1 - (int)blockIdx.x;
    const int bh = blockIdx.y;
    const int tx = threadIdx.x, ty = threadIdx.y;
    const int t  = ty * 16 + tx;
    const float scale = rsqrtf((float)D_);   // faithful: 1/sqrt(D)

    const float* Qg = g_q + (size_t)bh * HD_ * S_;   // [hd][s]
    const float* Kg = g_k + (size_t)bh * HD_ * S_;   // [hd][s]
    const float* Vg = g_v + (size_t)bh * S_ * HD_;   // [s][hd]

    const int q0 = qt * 64;

    // Load Q tile transposed-from-global (already [d][s]); coalesced float4.
    for (int i = t; i < 64 * 16; i += 256) {
        int d  = i >> 4;
        int r4 = (i & 15) * 4;
        float4 v = *(const float4*)(Qg + (size_t)d * S_ + q0 + r4);
        v.x *= scale; v.y *= scale; v.z *= scale; v.w *= scale;
        *(float4*)&Qt[d * PAD + r4] = v;
    }

    float acc[4][4] = {};
    float m_i[4], l_i[4];
    #pragma unroll
    for (int i = 0; i < 4; i++) { m_i[i] = -INFINITY; l_i[i] = 0.f; }

    __syncthreads();

    for (int kt = 0; kt <= qt; kt++) {
        const int k0 = kt * 64;
        // Load K (transposed-from-global) and V (natural); all float4.
        for (int i = t; i < 64 * 16; i += 256) {
            int a  = i >> 4;
            int c4 = (i & 15) * 4;
            *(float4*)&Kt[a * PAD + c4] =
                *(const float4*)(Kg + (size_t)a * S_ + k0 + c4);
            *(float4*)&Vs[a * PAD + c4] =
                *(const float4*)(Vg + (size_t)(k0 + a) * HD_ + c4);
        }
        __syncthreads();

        // S = Q K^T
        float s[4][4] = {};
        #pragma unroll 16
        for (int d = 0; d < 64; d++) {
            float4 a = *(const float4*)&Qt[d * PAD + 4 * ty];
            float4 b = *(const float4*)&Kt[d * PAD + 4 * tx];
            s[0][0] = fmaf(a.x, b.x, s[0][0]); s[0][1] = fmaf(a.x, b.y, s[0][1]);
            s[0][2] = fmaf(a.x, b.z, s[0][2]); s[0][3] = fmaf(a.x, b.w, s[0][3]);
            s[1][0] = fmaf(a.y, b.x, s[1][0]); s[1][1] = fmaf(a.y, b.y, s[1][1]);
            s[1][2] = fmaf(a.y, b.z, s[1][2]); s[1][3] = fmaf(a.y, b.w, s[1][3]);
            s[2][0] = fmaf(a.z, b.x, s[2][0]); s[2][1] = fmaf(a.z, b.y, s[2][1]);
            s[2][2] = fmaf(a.z, b.z, s[2][2]); s[2][3] = fmaf(a.z, b.w, s[2][3]);
            s[3][0] = fmaf(a.w, b.x, s[3][0]); s[3][1] = fmaf(a.w, b.y, s[3][1]);
            s[3][2] = fmaf(a.w, b.z, s[3][2]); s[3][3] = fmaf(a.w, b.w, s[3][3]);
        }

        if (kt == qt) {   // diagonal tile: causal mask
            #pragma unroll
            for (int i = 0; i < 4; i++)
                #pragma unroll
                for (int j = 0; j < 4; j++)
                    if (k0 + 4 * tx + j > q0 + 4 * ty + i) s[i][j] = -INFINITY;
        }

        // Row max across the 16-thread row group (offsets 1..8 stay in-half).
        float mnew[4];
        #pragma unroll
        for (int i = 0; i < 4; i++) {
            float mx = fmaxf(fmaxf(s[i][0], s[i][1]), fmaxf(s[i][2], s[i][3]));
            #pragma unroll
            for (int off = 1; off < 16; off <<= 1)
                mx = fmaxf(mx, __shfl_xor_sync(0xffffffffu, mx, off));
            mnew[i] = fmaxf(m_i[i], mx);
        }

        // p = exp(s - m); row sums.
        float rs[4];
        #pragma unroll
        for (int i = 0; i < 4; i++) {
            float sum = 0.f;
            #pragma unroll
            for (int j = 0; j < 4; j++) {
                float p = __expf(s[i][j] - mnew[i]);
                s[i][j] = p;
                sum += p;
            }
            #pragma unroll
            for (int off = 1; off < 16; off <<= 1)
                sum += __shfl_xor_sync(0xffffffffu, sum, off);
            rs[i] = sum;
        }

        // Rescale running state (exp(-inf)=0 covers the first tile).
        #pragma unroll
        for (int i = 0; i < 4; i++) {
            float corr = __expf(m_i[i] - mnew[i]);
            l_i[i] = l_i[i] * corr + rs[i];
            m_i[i] = mnew[i];
            #pragma unroll
            for (int j = 0; j < 4; j++) acc[i][j] *= corr;
        }

        // Stage P (STS.128 per row).
        #pragma unroll
        for (int i = 0; i < 4; i++)
            *(float4*)&Ps[(4 * ty + i) * PAD + 4 * tx] =
                make_float4(s[i][0], s[i][1], s[i][2], s[i][3]);
        __syncthreads();

        // acc += P V  (4-jj blocks: 8 LDS.128 + 64 FMA)
        #pragma unroll 4
        for (int j4 = 0; j4 < 64; j4 += 4) {
            float4 p0 = *(const float4*)&Ps[(4 * ty + 0) * PAD + j4];
            float4 p1 = *(const float4*)&Ps[(4 * ty + 1) * PAD + j4];
            float4 p2 = *(const float4*)&Ps[(4 * ty + 2) * PAD + j4];
            float4 p3 = *(const float4*)&Ps[(4 * ty + 3) * PAD + j4];
            float4 v0 = *(const float4*)&Vs[(j4 + 0) * PAD + 4 * tx];
            float4 v1 = *(const float4*)&Vs[(j4 + 1) * PAD + 4 * tx];
            float4 v2 = *(const float4*)&Vs[(j4 + 2) * PAD + 4 * tx];
            float4 v3 = *(const float4*)&Vs[(j4 + 3) * PAD + 4 * tx];
            #define PV_ROW(i, pi)                                              \
                acc[i][0] = fmaf(pi.x, v0.x, acc[i][0]);                       \
                acc[i][1] = fmaf(pi.x, v0.y, acc[i][1]);                       \
                acc[i][2] = fmaf(pi.x, v0.z, acc[i][2]);                       \
                acc[i][3] = fmaf(pi.x, v0.w, acc[i][3]);                       \
                acc[i][0] = fmaf(pi.y, v1.x, acc[i][0]);                       \
                acc[i][1] = fmaf(pi.y, v1.y, acc[i][1]);                       \
                acc[i][2] = fmaf(pi.y, v1.z, acc[i][2]);                       \
                acc[i][3] = fmaf(pi.y, v1.w, acc[i][3]);                       \
                acc[i][0] = fmaf(pi.z, v2.x, acc[i][0]);                       \
                acc[i][1] = fmaf(pi.z, v2.y, acc[i][1]);                       \
                acc[i][2] = fmaf(pi.z, v2.z, acc[i][2]);                       \
                acc[i][3] = fmaf(pi.z, v2.w, acc[i][3]);                       \
                acc[i][0] = fmaf(pi.w, v3.x, acc[i][0]);                       \
                acc[i][1] = fmaf(pi.w, v3.y, acc[i][1]);                       \
                acc[i][2] = fmaf(pi.w, v3.z, acc[i][2]);                       \
                acc[i][3] = fmaf(pi.w, v3.w, acc[i][3]);
            PV_ROW(0, p0) PV_ROW(1, p1) PV_ROW(2, p2) PV_ROW(3, p3)
            #undef PV_ROW
        }
        __syncthreads();
    }

    // Epilogue: normalize, write [B,S,D] (D index = h*64 + hd), float4 stores.
    const int b = bh >> 3;
    const int h = bh & 7;
    #pragma unroll
    for (int i = 0; i < 4; i++) {
        int srow  = q0 + 4 * ty + i;
        float inv = 1.f / l_i[i];
        float4 o  = make_float4(acc[i][0] * inv, acc[i][1] * inv,
                                acc[i][2] * inv, acc[i][3] * inv);
        *(float4*)&out[((size_t)(b * S_ + srow)) * D_ + h * HD_ + 4 * tx] = o;
    }
}

// ---------------------------------------------------------------------------
extern "C" void kernel_launch(void* const* d_in, const int* in_sizes, int n_in,
                              void* d_out, int out_size)
{
    const float* x  = (const float*)d_in[0];
    const float* Wq = (const float*)d_in[1];
    const float* bq = (const float*)d_in[2];
    const float* Wk = (const float*)d_in[3];
    const float* bk = (const float*)d_in[4];
    const float* Wv = (const float*)d_in[5];
    const float* bv = (const float*)d_in[6];
    float* out = (float*)d_out;

    dim3 blk(16, 16);
    qkv_gemm<<<dim3(D_ / 64, BS_ / 64, 3), blk>>>(x, Wq, bq, Wk, bk, Wv, bv);

    const int smem = 4 * 64 * PAD * (int)sizeof(float);  // 69,632 B
    cudaFuncSetAttribute(attn_kernel,
                         cudaFuncAttributeMaxDynamicSharedMemorySize, smem);
    attn_kernel<<<dim3(S_ / 64, B_ * H_), blk, smem>>>(out);
}

// round 6
// speedup vs baseline: 2.8837x; 2.8837x over previous
#include <cuda_runtime.h>
#include <cuda_bf16.h>
#include <cstdint>
#include <math.h>

#define B_  2
#define S_  4096
#define D_  512
#define H_  8
#define HD_ 64
#define BS_ (B_*S_)
#define PAD 68

// ===== bf16 hi/lo scratch (written by qkv_gemm, read by attention) =====
// qh/ql, kh/kl : [bh][s][hd]   (row-major over s; k-pairs contiguous in hd)
// vth/vtl      : [bh][hd][s]   (V transposed; PV B-frag k-pairs contiguous in s)
__device__ __nv_bfloat16 g_qh[B_*H_*S_*HD_];
__device__ __nv_bfloat16 g_ql[B_*H_*S_*HD_];
__device__ __nv_bfloat16 g_kh[B_*H_*S_*HD_];
__device__ __nv_bfloat16 g_kl[B_*H_*S_*HD_];
__device__ __nv_bfloat16 g_vth[B_*H_*HD_*S_];
__device__ __nv_bfloat16 g_vtl[B_*H_*HD_*S_];

__device__ __forceinline__ float ex2(float x) {
    float r; asm("ex2.approx.f32 %0, %1;" : "=f"(r) : "f"(x)); return r;
}

// m16n8k16 row.col bf16 MMA, fp32 accumulate (baseline ISA, sm_80+).
__device__ __forceinline__ void mma_bf16(float* d, const uint32_t* a,
                                         const uint32_t* b) {
    asm volatile(
        "mma.sync.aligned.m16n8k16.row.col.f32.bf16.bf16.f32 "
        "{%0,%1,%2,%3}, {%4,%5,%6,%7}, {%8,%9}, {%0,%1,%2,%3};"
        : "+f"(d[0]), "+f"(d[1]), "+f"(d[2]), "+f"(d[3])
        : "r"(a[0]), "r"(a[1]), "r"(a[2]), "r"(a[3]), "r"(b[0]), "r"(b[1]));
}

__device__ __forceinline__ uint32_t packbf(float a, float b) {
    __nv_bfloat162 t = __halves2bfloat162(__float2bfloat16(a),
                                          __float2bfloat16(b));
    return *reinterpret_cast<uint32_t*>(&t);
}

// ---------------------------------------------------------------------------
// Fused QKV projection (FFMA). Epilogue emits bf16 hi/lo:
//   z=0 -> Qh/Ql (scaled by 1/sqrt(512)*log2(e)), z=1 -> Kh/Kl, z=2 -> Vt h/l.
// ---------------------------------------------------------------------------
__global__ void __launch_bounds__(256) qkv_gemm(
    const float* __restrict__ x,
    const float* __restrict__ Wq, const float* __restrict__ bq,
    const float* __restrict__ Wk, const float* __restrict__ bk,
    const float* __restrict__ Wv, const float* __restrict__ bv)
{
    __shared__ float As[32][PAD];
    __shared__ float Bs[32][PAD];

    const int z = blockIdx.z;
    const float* W    = (z == 0) ? Wq : ((z == 1) ? Wk : Wv);
    const float* bias = (z == 0) ? bq : ((z == 1) ? bk : bv);

    const int m0 = blockIdx.y * 64;
    const int n0 = blockIdx.x * 64;
    const int tx = threadIdx.x, ty = threadIdx.y;
    const int t  = ty * 16 + tx;

    float acc[4][4] = {};

    for (int k0 = 0; k0 < D_; k0 += 32) {
        #pragma unroll
        for (int i = 0; i < 2; i++) {
            int f  = t + i * 256;
            int m  = f >> 3;
            int kq = (f & 7) * 4;
            float4 a4 = *(const float4*)(x + (size_t)(m0 + m) * D_ + k0 + kq);
            As[kq + 0][m] = a4.x; As[kq + 1][m] = a4.y;
            As[kq + 2][m] = a4.z; As[kq + 3][m] = a4.w;
            float4 w4 = *(const float4*)(W + (size_t)(n0 + m) * D_ + k0 + kq);
            Bs[kq + 0][m] = w4.x; Bs[kq + 1][m] = w4.y;
            Bs[kq + 2][m] = w4.z; Bs[kq + 3][m] = w4.w;
        }
        __syncthreads();

        #pragma unroll
        for (int k = 0; k < 32; k++) {
            float4 a = *(const float4*)&As[k][4 * ty];
            float4 b = *(const float4*)&Bs[k][4 * tx];
            acc[0][0] = fmaf(a.x, b.x, acc[0][0]); acc[0][1] = fmaf(a.x, b.y, acc[0][1]);
            acc[0][2] = fmaf(a.x, b.z, acc[0][2]); acc[0][3] = fmaf(a.x, b.w, acc[0][3]);
            acc[1][0] = fmaf(a.y, b.x, acc[1][0]); acc[1][1] = fmaf(a.y, b.y, acc[1][1]);
            acc[1][2] = fmaf(a.y, b.z, acc[1][2]); acc[1][3] = fmaf(a.y, b.w, acc[1][3]);
            acc[2][0] = fmaf(a.z, b.x, acc[2][0]); acc[2][1] = fmaf(a.z, b.y, acc[2][1]);
            acc[2][2] = fmaf(a.z, b.z, acc[2][2]); acc[2][3] = fmaf(a.z, b.w, acc[2][3]);
            acc[3][0] = fmaf(a.w, b.x, acc[3][0]); acc[3][1] = fmaf(a.w, b.y, acc[3][1]);
            acc[3][2] = fmaf(a.w, b.z, acc[3][2]); acc[3][3] = fmaf(a.w, b.w, acc[3][3]);
        }
        __syncthreads();
    }

    const int row0 = m0 + 4 * ty;
    const int b    = row0 >> 12;
    const int s0   = row0 & 4095;
    float4 bn4 = *(const float4*)&bias[n0 + 4 * tx];
    const float bn[4] = { bn4.x, bn4.y, bn4.z, bn4.w };
    // scores computed in log2 domain: fold 1/sqrt(512)*log2(e) into Q.
    const float QS = 0.044194173824159216f * 1.4426950408889634f;

    if (z < 2) {
        __nv_bfloat16* dh = (z == 0) ? g_qh : g_kh;
        __nv_bfloat16* dl = (z == 0) ? g_ql : g_kl;
        const float sc = (z == 0) ? QS : 1.0f;
        const int n  = n0 + 4 * tx;
        const int h  = n >> 6;
        const int hd = n & 63;
        #pragma unroll
        for (int i = 0; i < 4; i++) {
            size_t base = (((size_t)(b * H_ + h)) * S_ + (s0 + i)) * HD_ + hd;
            #pragma unroll
            for (int j = 0; j < 4; j += 2) {
                float y0 = (acc[i][j]     + bn[j])     * sc;
                float y1 = (acc[i][j + 1] + bn[j + 1]) * sc;
                __nv_bfloat16 h0 = __float2bfloat16(y0);
                __nv_bfloat16 h1 = __float2bfloat16(y1);
                float r0 = y0 - __bfloat162float(h0);
                float r1 = y1 - __bfloat162float(h1);
                *(__nv_bfloat162*)&dh[base + j] = __halves2bfloat162(h0, h1);
                *(__nv_bfloat162*)&dl[base + j] = __halves2bfloat162(
                    __float2bfloat16(r0), __float2bfloat16(r1));
            }
        }
    } else {
        // V transposed: [bh][hd][s]
        #pragma unroll
        for (int j = 0; j < 4; j++) {
            int n  = n0 + 4 * tx + j;
            int h  = n >> 6;
            int hd = n & 63;
            size_t base = (((size_t)(b * H_ + h)) * HD_ + hd) * S_ + s0;
            #pragma unroll
            for (int i = 0; i < 4; i += 2) {
                float y0 = acc[i][j]     + bn[j];
                float y1 = acc[i + 1][j] + bn[j];
                __nv_bfloat16 h0 = __float2bfloat16(y0);
                __nv_bfloat16 h1 = __float2bfloat16(y1);
                float r0 = y0 - __bfloat162float(h0);
                float r1 = y1 - __bfloat162float(h1);
                *(__nv_bfloat162*)&g_vth[base + i] = __halves2bfloat162(h0, h1);
                *(__nv_bfloat162*)&g_vtl[base + i] = __halves2bfloat162(
                    __float2bfloat16(r0), __float2bfloat16(r1));
            }
        }
    }
}

// ---------------------------------------------------------------------------
// mma.sync causal flash attention. 256 threads / 8 warps. Br=128, Bc=64.
// Warp w owns q-rows [w*16, w*16+16); per k-tile it computes S[16][64] with
// 8 m16n8k16 n-frags, 3-term hi/lo bf16 emulation, then O += P·V likewise.
// P stays in registers (S-frag cols == P A-frag k-cols). 144 B row pitch
// makes all fragment LDS conflict-free.
// ---------------------------------------------------------------------------
#define BR 128
#define BC 64
#define RP 144                      // smem row pitch (64 bf16 = 128 B + 16)

#define SQH 0
#define SQL (SQH + BR*RP)           // 18432
#define SKH (SQL + BR*RP)           // 36864
#define SKL (SKH + BC*RP)           // 46080
#define SVH (SKL + BC*RP)           // 55296
#define SVL (SVH + 64*RP)           // 64512
#define SMTOT (SVL + 64*RP)         // 73728

__global__ void __launch_bounds__(256) attn_kernel(float* __restrict__ out)
{
    extern __shared__ uint8_t sm[];
    const int tid  = threadIdx.x;
    const int wid  = tid >> 5;
    const int lane = tid & 31;
    const int g    = lane >> 2;      // group (row within 8)
    const int c    = lane & 3;       // thread-in-group (k/col pair index)

    const int qt = 31 - (int)blockIdx.x;   // heavy q-tiles first
    const int bh = blockIdx.y;
    const int q0 = qt * BR;

    // ---- load Q tile (hi/lo): 128 rows x 64 bf16 ----
    {
        const __nv_bfloat16* qh = g_qh + ((size_t)bh * S_ + q0) * HD_;
        const __nv_bfloat16* ql = g_ql + ((size_t)bh * S_ + q0) * HD_;
        for (int i = tid; i < BR * 8; i += 256) {
            int r = i >> 3, c8 = i & 7;
            *(uint4*)(sm + SQH + r * RP + c8 * 16) =
                *(const uint4*)(qh + r * HD_ + c8 * 8);
            *(uint4*)(sm + SQL + r * RP + c8 * 16) =
                *(const uint4*)(ql + r * HD_ + c8 * 8);
        }
    }

    float o[8][4];
    #pragma unroll
    for (int j = 0; j < 8; j++) { o[j][0] = o[j][1] = o[j][2] = o[j][3] = 0.f; }
    float m0 = -INFINITY, m1 = -INFINITY, l0 = 0.f, l1 = 0.f;

    const int r0 = q0 + wid * 16 + g;   // this thread's two q-rows
    const int r1 = r0 + 8;

    const int nkt = 2 * qt + 2;
    for (int kt = 0; kt < nkt; kt++) {
        const int k0 = kt * BC;
        __syncthreads();   // previous iteration's smem reads complete
        {
            const __nv_bfloat16* kh = g_kh + ((size_t)bh * S_ + k0) * HD_;
            const __nv_bfloat16* kl = g_kl + ((size_t)bh * S_ + k0) * HD_;
            const __nv_bfloat16* vh = g_vth + (size_t)bh * HD_ * S_ + k0;
            const __nv_bfloat16* vl = g_vtl + (size_t)bh * HD_ * S_ + k0;
            for (int i = tid; i < BC * 8; i += 256) {
                int r = i >> 3, c8 = i & 7;
                *(uint4*)(sm + SKH + r * RP + c8 * 16) =
                    *(const uint4*)(kh + r * HD_ + c8 * 8);
                *(uint4*)(sm + SKL + r * RP + c8 * 16) =
                    *(const uint4*)(kl + r * HD_ + c8 * 8);
                *(uint4*)(sm + SVH + r * RP + c8 * 16) =
                    *(const uint4*)(vh + (size_t)r * S_ + c8 * 8);
                *(uint4*)(sm + SVL + r * RP + c8 * 16) =
                    *(const uint4*)(vl + (size_t)r * S_ + c8 * 8);
            }
        }
        __syncthreads();

        // ---- S[16][64] = Qh·Kh^T + Qh·Kl^T + Ql·Kh^T ----
        float s[8][4];
        #pragma unroll
        for (int j = 0; j < 8; j++) { s[j][0] = s[j][1] = s[j][2] = s[j][3] = 0.f; }

        #pragma unroll
        for (int ks = 0; ks < 4; ks++) {
            const uint32_t arow0 = (wid * 16 + g)     * RP + ks * 32 + c * 4;
            const uint32_t arow1 = (wid * 16 + g + 8) * RP + ks * 32 + c * 4;
            uint32_t ah[4], al[4];
            ah[0] = *(const uint32_t*)(sm + SQH + arow0);
            ah[1] = *(const uint32_t*)(sm + SQH + arow1);
            ah[2] = *(const uint32_t*)(sm + SQH + arow0 + 16);
            ah[3] = *(const uint32_t*)(sm + SQH + arow1 + 16);
            al[0] = *(const uint32_t*)(sm + SQL + arow0);
            al[1] = *(const uint32_t*)(sm + SQL + arow1);
            al[2] = *(const uint32_t*)(sm + SQL + arow0 + 16);
            al[3] = *(const uint32_t*)(sm + SQL + arow1 + 16);
            #pragma unroll
            for (int j = 0; j < 8; j++) {
                const uint32_t koff = (8 * j + g) * RP + ks * 32 + c * 4;
                uint32_t bhf[2], blf[2];
                bhf[0] = *(const uint32_t*)(sm + SKH + koff);
                bhf[1] = *(const uint32_t*)(sm + SKH + koff + 16);
                blf[0] = *(const uint32_t*)(sm + SKL + koff);
                blf[1] = *(const uint32_t*)(sm + SKL + koff + 16);
                mma_bf16(s[j], ah, bhf);
                mma_bf16(s[j], ah, blf);
                mma_bf16(s[j], al, bhf);
            }
        }

        // ---- causal mask (only tiles overlapping the diagonal band) ----
        if (kt >= 2 * qt) {
            #pragma unroll
            for (int j = 0; j < 8; j++) {
                int col = k0 + 8 * j + 2 * c;
                if (col     > r0) s[j][0] = -INFINITY;
                if (col + 1 > r0) s[j][1] = -INFINITY;
                if (col     > r1) s[j][2] = -INFINITY;
                if (col + 1 > r1) s[j][3] = -INFINITY;
            }
        }

        // ---- online softmax (log2 domain; scale folded into Q) ----
        float mx0 = -INFINITY, mx1 = -INFINITY;
        #pragma unroll
        for (int j = 0; j < 8; j++) {
            mx0 = fmaxf(mx0, fmaxf(s[j][0], s[j][1]));
            mx1 = fmaxf(mx1, fmaxf(s[j][2], s[j][3]));
        }
        mx0 = fmaxf(mx0, __shfl_xor_sync(0xffffffffu, mx0, 1));
        mx0 = fmaxf(mx0, __shfl_xor_sync(0xffffffffu, mx0, 2));
        mx1 = fmaxf(mx1, __shfl_xor_sync(0xffffffffu, mx1, 1));
        mx1 = fmaxf(mx1, __shfl_xor_sync(0xffffffffu, mx1, 2));
        const float mn0 = fmaxf(m0, mx0), mn1 = fmaxf(m1, mx1);
        const float cr0 = ex2(m0 - mn0),  cr1 = ex2(m1 - mn1);
        m0 = mn0; m1 = mn1;

        uint32_t phr0[8], phr1[8], plr0[8], plr1[8];
        float ls0 = 0.f, ls1 = 0.f;
        #pragma unroll
        for (int j = 0; j < 8; j++) {
            float p00 = ex2(s[j][0] - mn0), p01 = ex2(s[j][1] - mn0);
            float p10 = ex2(s[j][2] - mn1), p11 = ex2(s[j][3] - mn1);
            ls0 += p00 + p01; ls1 += p10 + p11;
            __nv_bfloat16 h00 = __float2bfloat16(p00);
            __nv_bfloat16 h01 = __float2bfloat16(p01);
            __nv_bfloat16 h10 = __float2bfloat16(p10);
            __nv_bfloat16 h11 = __float2bfloat16(p11);
            __nv_bfloat162 t0 = __halves2bfloat162(h00, h01);
            __nv_bfloat162 t1 = __halves2bfloat162(h10, h11);
            phr0[j] = *reinterpret_cast<uint32_t*>(&t0);
            phr1[j] = *reinterpret_cast<uint32_t*>(&t1);
            plr0[j] = packbf(p00 - __bfloat162float(h00),
                             p01 - __bfloat162float(h01));
            plr1[j] = packbf(p10 - __bfloat162float(h10),
                             p11 - __bfloat162float(h11));
        }
        l0 = l0 * cr0 + ls0;            // per-lane partial; reduced at end
        l1 = l1 * cr1 + ls1;
        #pragma unroll
        for (int j = 0; j < 8; j++) {
            o[j][0] *= cr0; o[j][1] *= cr0;
            o[j][2] *= cr1; o[j][3] *= cr1;
        }

        // ---- O[16][64] += Ph·Vh + Ph·Vl + Pl·Vh (P from registers) ----
        #pragma unroll
        for (int ks = 0; ks < 4; ks++) {
            uint32_t pa[4] = { phr0[2*ks], phr1[2*ks], phr0[2*ks+1], phr1[2*ks+1] };
            uint32_t pb[4] = { plr0[2*ks], plr1[2*ks], plr0[2*ks+1], plr1[2*ks+1] };
            #pragma unroll
            for (int j = 0; j < 8; j++) {
                const uint32_t voff = (8 * j + g) * RP + ks * 32 + c * 4;
                uint32_t vbh[2], vbl[2];
                vbh[0] = *(const uint32_t*)(sm + SVH + voff);
                vbh[1] = *(const uint32_t*)(sm + SVH + voff + 16);
                vbl[0] = *(const uint32_t*)(sm + SVL + voff);
                vbl[1] = *(const uint32_t*)(sm + SVL + voff + 16);
                mma_bf16(o[j], pa, vbh);
                mma_bf16(o[j], pa, vbl);
                mma_bf16(o[j], pb, vbh);
            }
        }
    }

    // ---- epilogue: reduce l across quad, normalize, store [B,S,D] ----
    l0 += __shfl_xor_sync(0xffffffffu, l0, 1);
    l0 += __shfl_xor_sync(0xffffffffu, l0, 2);
    l1 += __shfl_xor_sync(0xffffffffu, l1, 1);
    l1 += __shfl_xor_sync(0xffffffffu, l1, 2);
    const float inv0 = 1.f / l0, inv1 = 1.f / l1;
    const int b = bh >> 3, h = bh & 7;
    float* d0 = out + ((size_t)(b * S_ + r0)) * D_ + h * HD_;
    float* d1 = out + ((size_t)(b * S_ + r1)) * D_ + h * HD_;
    #pragma unroll
    for (int j = 0; j < 8; j++) {
        const int col = 8 * j + 2 * c;
        *(float2*)(d0 + col) = make_float2(o[j][0] * inv0, o[j][1] * inv0);
        *(float2*)(d1 + col) = make_float2(o[j][2] * inv1, o[j][3] * inv1);
    }
}

// ---------------------------------------------------------------------------
extern "C" void kernel_launch(void* const* d_in, const int* in_sizes, int n_in,
                              void* d_out, int out_size)
{
    const float* x  = (const float*)d_in[0];
    const float* Wq = (const float*)d_in[1];
    const float* bq = (const float*)d_in[2];
    const float* Wk = (const float*)d_in[3];
    const float* bk = (const float*)d_in[4];
    const float* Wv = (const float*)d_in[5];
    const float* bv = (const float*)d_in[6];
    float* out = (float*)d_out;

    dim3 blk(16, 16);
    qkv_gemm<<<dim3(D_ / 64, BS_ / 64, 3), blk>>>(x, Wq, bq, Wk, bk, Wv, bv);

    cudaFuncSetAttribute(attn_kernel,
                         cudaFuncAttributeMaxDynamicSharedMemorySize, SMTOT);
    attn_kernel<<<dim3(S_ / BR, B_ * H_), 256, SMTOT>>>(out);
}

// round 8
// speedup vs baseline: 4.0877x; 1.4175x over previous
#include <cuda_runtime.h>
#include <cuda_bf16.h>
#include <cstdint>
#include <math.h>

#define B_  2
#define S_  4096
#define D_  512
#define H_  8
#define HD_ 64
#define BS_ (B_*S_)

// ===== bf16 hi/lo scratch (written by qkv_gemm, read by attention) =====
// qh/ql, kh/kl : [bh][s][hd]   (row-major over s; k-pairs contiguous in hd)
// vth/vtl      : [bh][hd][s]   (V transposed; PV B-frag k-pairs contiguous in s)
__device__ __nv_bfloat16 g_qh[B_*H_*S_*HD_];
__device__ __nv_bfloat16 g_ql[B_*H_*S_*HD_];
__device__ __nv_bfloat16 g_kh[B_*H_*S_*HD_];
__device__ __nv_bfloat16 g_kl[B_*H_*S_*HD_];
__device__ __nv_bfloat16 g_vth[B_*H_*HD_*S_];
__device__ __nv_bfloat16 g_vtl[B_*H_*HD_*S_];

__device__ __forceinline__ float ex2(float x) {
    float r; asm("ex2.approx.f32 %0, %1;" : "=f"(r) : "f"(x)); return r;
}

// m16n8k16 row.col bf16 MMA, fp32 accumulate (baseline ISA, sm_80+).
__device__ __forceinline__ void mma_bf16(float* d, const uint32_t* a,
                                         const uint32_t* b) {
    asm volatile(
        "mma.sync.aligned.m16n8k16.row.col.f32.bf16.bf16.f32 "
        "{%0,%1,%2,%3}, {%4,%5,%6,%7}, {%8,%9}, {%0,%1,%2,%3};"
        : "+f"(d[0]), "+f"(d[1]), "+f"(d[2]), "+f"(d[3])
        : "r"(a[0]), "r"(a[1]), "r"(a[2]), "r"(a[3]), "r"(b[0]), "r"(b[1]));
}

__device__ __forceinline__ uint32_t packbf(float a, float b) {
    __nv_bfloat162 t = __halves2bfloat162(__float2bfloat16(a),
                                          __float2bfloat16(b));
    return *reinterpret_cast<uint32_t*>(&t);
}
// split (x, y) into hi/lo bf16 pair-packed words
__device__ __forceinline__ void split2(float x, float y, uint32_t& hi, uint32_t& lo) {
    __nv_bfloat16 hx = __float2bfloat16(x);
    __nv_bfloat16 hy = __float2bfloat16(y);
    __nv_bfloat162 th = __halves2bfloat162(hx, hy);
    hi = *reinterpret_cast<uint32_t*>(&th);
    lo = packbf(x - __bfloat162float(hx), y - __bfloat162float(hy));
}

// ---------------------------------------------------------------------------
// Fused QKV projection on mma.sync bf16 hi/lo (3-term: XhWh + XhWl + XlWh).
// BM=128, BN=64, BK=32; 8 warps, warp = m16 x n64 (8 n-frags).
// fp32 tiles staged in registers (double-buffers the global load), split
// hi/lo on the smem store. Pitch 80 B => conflict-free fragment LDS.
// Epilogue emits bf16 hi/lo scratch:
//   z=0 -> Qh/Ql (scaled by 1/sqrt(512)*log2(e)), z=1 -> Kh/Kl, z=2 -> Vt h/l.
// ---------------------------------------------------------------------------
#define GP 80                       // smem pitch bytes (32 bf16 = 64 B + 16)
#define GXH 0
#define GXL (GXH + 128*GP)          // 10240
#define GWH (GXL + 128*GP)          // 20480
#define GWL (GWH + 64*GP)           // 25600
#define GSM (GWL + 64*GP)           // 30720

__global__ void __launch_bounds__(256) qkv_gemm(
    const float* __restrict__ x,
    const float* __restrict__ Wq, const float* __restrict__ bq,
    const float* __restrict__ Wk, const float* __restrict__ bk,
    const float* __restrict__ Wv, const float* __restrict__ bv)
{
    __shared__ uint8_t sm[GSM];

    const int z = blockIdx.z;
    const float* W    = (z == 0) ? Wq : ((z == 1) ? Wk : Wv);
    const float* bias = (z == 0) ? bq : ((z == 1) ? bk : bv);

    const int bm = blockIdx.y * 128;
    const int bn = blockIdx.x * 64;
    const int tid  = threadIdx.x;
    const int wid  = tid >> 5;
    const int lane = tid & 31;
    const int g    = lane >> 2;
    const int c    = lane & 3;

    // loader indices: x tile 128x32 fp32 (4 float4/thr), W tile 64x32 (2/thr)
    const int lr = tid >> 3;           // 0..31
    const int lc = (tid & 7) * 4;      // float col 0..28

    float4 xr[4], wr[2];

    float acc[8][4];
    #pragma unroll
    for (int j = 0; j < 8; j++) { acc[j][0]=acc[j][1]=acc[j][2]=acc[j][3]=0.f; }

    // preload chunk 0
    #pragma unroll
    for (int n = 0; n < 4; n++)
        xr[n] = *(const float4*)(x + (size_t)(bm + lr + 32*n) * D_ + lc);
    #pragma unroll
    for (int n = 0; n < 2; n++)
        wr[n] = *(const float4*)(W + (size_t)(bn + lr + 32*n) * D_ + lc);

    for (int k0 = 0; k0 < D_; k0 += 32) {
        __syncthreads();               // previous compute done reading smem
        // store staged regs -> smem as hi/lo bf16
        #pragma unroll
        for (int n = 0; n < 4; n++) {
            uint32_t h0, l0, h1, l1;
            split2(xr[n].x, xr[n].y, h0, l0);
            split2(xr[n].z, xr[n].w, h1, l1);
            uint32_t off = (uint32_t)(lr + 32*n) * GP + (uint32_t)lc * 2;
            *(uint32_t*)(sm + GXH + off)     = h0;
            *(uint32_t*)(sm + GXH + off + 4) = h1;
            *(uint32_t*)(sm + GXL + off)     = l0;
            *(uint32_t*)(sm + GXL + off + 4) = l1;
        }
        #pragma unroll
        for (int n = 0; n < 2; n++) {
            uint32_t h0, l0, h1, l1;
            split2(wr[n].x, wr[n].y, h0, l0);
            split2(wr[n].z, wr[n].w, h1, l1);
            uint32_t off = (uint32_t)(lr + 32*n) * GP + (uint32_t)lc * 2;
            *(uint32_t*)(sm + GWH + off)     = h0;
            *(uint32_t*)(sm + GWH + off + 4) = h1;
            *(uint32_t*)(sm + GWL + off)     = l0;
            *(uint32_t*)(sm + GWL + off + 4) = l1;
        }
        __syncthreads();

        // stage next chunk (overlaps with MMAs below via scoreboard)
        if (k0 + 32 < D_) {
            #pragma unroll
            for (int n = 0; n < 4; n++)
                xr[n] = *(const float4*)(x + (size_t)(bm + lr + 32*n) * D_ +
                                         k0 + 32 + lc);
            #pragma unroll
            for (int n = 0; n < 2; n++)
                wr[n] = *(const float4*)(W + (size_t)(bn + lr + 32*n) * D_ +
                                         k0 + 32 + lc);
        }

        // MMAs: 2 k-steps x 8 n-frags x 3 terms
        #pragma unroll
        for (int ks = 0; ks < 2; ks++) {
            const uint32_t a0 = (uint32_t)(wid * 16 + g)     * GP + ks * 32 + c * 4;
            const uint32_t a1 = (uint32_t)(wid * 16 + g + 8) * GP + ks * 32 + c * 4;
            uint32_t ah[4], al[4];
            ah[0] = *(const uint32_t*)(sm + GXH + a0);
            ah[1] = *(const uint32_t*)(sm + GXH + a1);
            ah[2] = *(const uint32_t*)(sm + GXH + a0 + 16);
            ah[3] = *(const uint32_t*)(sm + GXH + a1 + 16);
            al[0] = *(const uint32_t*)(sm + GXL + a0);
            al[1] = *(const uint32_t*)(sm + GXL + a1);
            al[2] = *(const uint32_t*)(sm + GXL + a0 + 16);
            al[3] = *(const uint32_t*)(sm + GXL + a1 + 16);
            #pragma unroll
            for (int j = 0; j < 8; j++) {
                const uint32_t bo = (uint32_t)(8 * j + g) * GP + ks * 32 + c * 4;
                uint32_t bh2[2], bl2[2];
                bh2[0] = *(const uint32_t*)(sm + GWH + bo);
                bh2[1] = *(const uint32_t*)(sm + GWH + bo + 16);
                bl2[0] = *(const uint32_t*)(sm + GWL + bo);
                bl2[1] = *(const uint32_t*)(sm + GWL + bo + 16);
                mma_bf16(acc[j], ah, bh2);
                mma_bf16(acc[j], ah, bl2);
                mma_bf16(acc[j], al, bh2);
            }
        }
    }

    // ---- epilogue from fragment layout ----
    const int r0 = bm + wid * 16 + g;     // global m rows (r1 = r0 + 8)
    const int b  = r0 >> 12;
    const int s0 = r0 & 4095;             // s for r0; r1 -> s0 + 8 (same b)
    const float QS = 0.044194173824159216f * 1.4426950408889634f;

    if (z < 2) {
        __nv_bfloat16* dh = (z == 0) ? g_qh : g_kh;
        __nv_bfloat16* dl = (z == 0) ? g_ql : g_kl;
        const float sc = (z == 0) ? QS : 1.0f;
        #pragma unroll
        for (int j = 0; j < 8; j++) {
            const int n  = bn + 8 * j + 2 * c;
            const int h  = n >> 6;
            const int hd = n & 63;
            float2 bv2 = *(const float2*)&bias[n];
            size_t base0 = (((size_t)(b * H_ + h)) * S_ + s0)     * HD_ + hd;
            size_t base1 = (((size_t)(b * H_ + h)) * S_ + s0 + 8) * HD_ + hd;
            uint32_t hi, lo;
            split2((acc[j][0] + bv2.x) * sc, (acc[j][1] + bv2.y) * sc, hi, lo);
            *(uint32_t*)&dh[base0] = hi;  *(uint32_t*)&dl[base0] = lo;
            split2((acc[j][2] + bv2.x) * sc, (acc[j][3] + bv2.y) * sc, hi, lo);
            *(uint32_t*)&dh[base1] = hi;  *(uint32_t*)&dl[base1] = lo;
        }
    } else {
        // V transposed [bh][hd][s]: per-element bf16 stores (warp gives
        // 8-consecutive-s runs per (hd) -> 16B coalesced segments).
        #pragma unroll
        for (int j = 0; j < 8; j++) {
            const int n  = bn + 8 * j + 2 * c;
            const int h  = n >> 6;
            const int hd = n & 63;
            float2 bv2 = *(const float2*)&bias[n];
            size_t c0 = (((size_t)(b * H_ + h)) * HD_ + hd)     * S_;
            size_t c1 = (((size_t)(b * H_ + h)) * HD_ + hd + 1) * S_;
            float v00 = acc[j][0] + bv2.x, v01 = acc[j][1] + bv2.y;
            float v10 = acc[j][2] + bv2.x, v11 = acc[j][3] + bv2.y;
            __nv_bfloat16 h00 = __float2bfloat16(v00);
            __nv_bfloat16 h01 = __float2bfloat16(v01);
            __nv_bfloat16 h10 = __float2bfloat16(v10);
            __nv_bfloat16 h11 = __float2bfloat16(v11);
            g_vth[c0 + s0]     = h00;
            g_vth[c1 + s0]     = h01;
            g_vth[c0 + s0 + 8] = h10;
            g_vth[c1 + s0 + 8] = h11;
            g_vtl[c0 + s0]     = __float2bfloat16(v00 - __bfloat162float(h00));
            g_vtl[c1 + s0]     = __float2bfloat16(v01 - __bfloat162float(h01));
            g_vtl[c0 + s0 + 8] = __float2bfloat16(v10 - __bfloat162float(h10));
            g_vtl[c1 + s0 + 8] = __float2bfloat16(v11 - __bfloat162float(h11));
        }
    }
}

// ---------------------------------------------------------------------------
// mma.sync causal flash attention (unchanged from R6 win). 256 thr / 8 warps.
// Br=128, Bc=64. 3-term hi/lo bf16; P stays in registers. RP=144 pitch.
// ---------------------------------------------------------------------------
#define BR 128
#define BC 64
#define RP 144

#define SQH 0
#define SQL (SQH + BR*RP)
#define SKH (SQL + BR*RP)
#define SKL (SKH + BC*RP)
#define SVH (SKL + BC*RP)
#define SVL (SVH + 64*RP)
#define SMTOT (SVL + 64*RP)

__global__ void __launch_bounds__(256) attn_kernel(float* __restrict__ out)
{
    extern __shared__ uint8_t sm[];
    const int tid  = threadIdx.x;
    const int wid  = tid >> 5;
    const int lane = tid & 31;
    const int g    = lane >> 2;
    const int c    = lane & 3;

    const int qt = 31 - (int)blockIdx.x;
    const int bh = blockIdx.y;
    const int q0 = qt * BR;

    {
        const __nv_bfloat16* qh = g_qh + ((size_t)bh * S_ + q0) * HD_;
        const __nv_bfloat16* ql = g_ql + ((size_t)bh * S_ + q0) * HD_;
        for (int i = tid; i < BR * 8; i += 256) {
            int r = i >> 3, c8 = i & 7;
            *(uint4*)(sm + SQH + r * RP + c8 * 16) =
                *(const uint4*)(qh + r * HD_ + c8 * 8);
            *(uint4*)(sm + SQL + r * RP + c8 * 16) =
                *(const uint4*)(ql + r * HD_ + c8 * 8);
        }
    }

    float o[8][4];
    #pragma unroll
    for (int j = 0; j < 8; j++) { o[j][0] = o[j][1] = o[j][2] = o[j][3] = 0.f; }
    float m0 = -INFINITY, m1 = -INFINITY, l0 = 0.f, l1 = 0.f;

    const int r0 = q0 + wid * 16 + g;
    const int r1 = r0 + 8;

    const int nkt = 2 * qt + 2;
    for (int kt = 0; kt < nkt; kt++) {
        const int k0 = kt * BC;
        __syncthreads();
        {
            const __nv_bfloat16* kh = g_kh + ((size_t)bh * S_ + k0) * HD_;
            const __nv_bfloat16* kl = g_kl + ((size_t)bh * S_ + k0) * HD_;
            const __nv_bfloat16* vh = g_vth + (size_t)bh * HD_ * S_ + k0;
            const __nv_bfloat16* vl = g_vtl + (size_t)bh * HD_ * S_ + k0;
            for (int i = tid; i < BC * 8; i += 256) {
                int r = i >> 3, c8 = i & 7;
                *(uint4*)(sm + SKH + r * RP + c8 * 16) =
                    *(const uint4*)(kh + r * HD_ + c8 * 8);
                *(uint4*)(sm + SKL + r * RP + c8 * 16) =
                    *(const uint4*)(kl + r * HD_ + c8 * 8);
                *(uint4*)(sm + SVH + r * RP + c8 * 16) =
                    *(const uint4*)(vh + (size_t)r * S_ + c8 * 8);
                *(uint4*)(sm + SVL + r * RP + c8 * 16) =
                    *(const uint4*)(vl + (size_t)r * S_ + c8 * 8);
            }
        }
        __syncthreads();

        float s[8][4];
        #pragma unroll
        for (int j = 0; j < 8; j++) { s[j][0] = s[j][1] = s[j][2] = s[j][3] = 0.f; }

        #pragma unroll
        for (int ks = 0; ks < 4; ks++) {
            const uint32_t arow0 = (wid * 16 + g)     * RP + ks * 32 + c * 4;
            const uint32_t arow1 = (wid * 16 + g + 8) * RP + ks * 32 + c * 4;
            uint32_t ah[4], al[4];
            ah[0] = *(const uint32_t*)(sm + SQH + arow0);
            ah[1] = *(const uint32_t*)(sm + SQH + arow1);
            ah[2] = *(const uint32_t*)(sm + SQH + arow0 + 16);
            ah[3] = *(const uint32_t*)(sm + SQH + arow1 + 16);
            al[0] = *(const uint32_t*)(sm + SQL + arow0);
            al[1] = *(const uint32_t*)(sm + SQL + arow1);
            al[2] = *(const uint32_t*)(sm + SQL + arow0 + 16);
            al[3] = *(const uint32_t*)(sm + SQL + arow1 + 16);
            #pragma unroll
            for (int j = 0; j < 8; j++) {
                const uint32_t koff = (8 * j + g) * RP + ks * 32 + c * 4;
                uint32_t bhf[2], blf[2];
                bhf[0] = *(const uint32_t*)(sm + SKH + koff);
                bhf[1] = *(const uint32_t*)(sm + SKH + koff + 16);
                blf[0] = *(const uint32_t*)(sm + SKL + koff);
                blf[1] = *(const uint32_t*)(sm + SKL + koff + 16);
                mma_bf16(s[j], ah, bhf);
                mma_bf16(s[j], ah, blf);
                mma_bf16(s[j], al, bhf);
            }
        }

        if (kt >= 2 * qt) {
            #pragma unroll
            for (int j = 0; j < 8; j++) {
                int col = k0 + 8 * j + 2 * c;
                if (col     > r0) s[j][0] = -INFINITY;
                if (col + 1 > r0) s[j][1] = -INFINITY;
                if (col     > r1) s[j][2] = -INFINITY;
                if (col + 1 > r1) s[j][3] = -INFINITY;
            }
        }

        float mx0 = -INFINITY, mx1 = -INFINITY;
        #pragma unroll
        for (int j = 0; j < 8; j++) {
            mx0 = fmaxf(mx0, fmaxf(s[j][0], s[j][1]));
            mx1 = fmaxf(mx1, fmaxf(s[j][2], s[j][3]));
        }
        mx0 = fmaxf(mx0, __shfl_xor_sync(0xffffffffu, mx0, 1));
        mx0 = fmaxf(mx0, __shfl_xor_sync(0xffffffffu, mx0, 2));
        mx1 = fmaxf(mx1, __shfl_xor_sync(0xffffffffu, mx1, 1));
        mx1 = fmaxf(mx1, __shfl_xor_sync(0xffffffffu, mx1, 2));
        const float mn0 = fmaxf(m0, mx0), mn1 = fmaxf(m1, mx1);
        const float cr0 = ex2(m0 - mn0),  cr1 = ex2(m1 - mn1);
        m0 = mn0; m1 = mn1;

        uint32_t phr0[8], phr1[8], plr0[8], plr1[8];
        float ls0 = 0.f, ls1 = 0.f;
        #pragma unroll
        for (int j = 0; j < 8; j++) {
            float p00 = ex2(s[j][0] - mn0), p01 = ex2(s[j][1] - mn0);
            float p10 = ex2(s[j][2] - mn1), p11 = ex2(s[j][3] - mn1);
            ls0 += p00 + p01; ls1 += p10 + p11;
            __nv_bfloat16 h00 = __float2bfloat16(p00);
            __nv_bfloat16 h01 = __float2bfloat16(p01);
            __nv_bfloat16 h10 = __float2bfloat16(p10);
            __nv_bfloat16 h11 = __float2bfloat16(p11);
            __nv_bfloat162 t0 = __halves2bfloat162(h00, h01);
            __nv_bfloat162 t1 = __halves2bfloat162(h10, h11);
            phr0[j] = *reinterpret_cast<uint32_t*>(&t0);
            phr1[j] = *reinterpret_cast<uint32_t*>(&t1);
            plr0[j] = packbf(p00 - __bfloat162float(h00),
                             p01 - __bfloat162float(h01));
            plr1[j] = packbf(p10 - __bfloat162float(h10),
                             p11 - __bfloat162float(h11));
        }
        l0 = l0 * cr0 + ls0;
        l1 = l1 * cr1 + ls1;
        #pragma unroll
        for (int j = 0; j < 8; j++) {
            o[j][0] *= cr0; o[j][1] *= cr0;
            o[j][2] *= cr1; o[j][3] *= cr1;
        }

        #pragma unroll
        for (int ks = 0; ks < 4; ks++) {
            uint32_t pa[4] = { phr0[2*ks], phr1[2*ks], phr0[2*ks+1], phr1[2*ks+1] };
            uint32_t pb[4] = { plr0[2*ks], plr1[2*ks], plr0[2*ks+1], plr1[2*ks+1] };
            #pragma unroll
            for (int j = 0; j < 8; j++) {
                const uint32_t voff = (8 * j + g) * RP + ks * 32 + c * 4;
                uint32_t vbh[2], vbl[2];
                vbh[0] = *(const uint32_t*)(sm + SVH + voff);
                vbh[1] = *(const uint32_t*)(sm + SVH + voff + 16);
                vbl[0] = *(const uint32_t*)(sm + SVL + voff);
                vbl[1] = *(const uint32_t*)(sm + SVL + voff + 16);
                mma_bf16(o[j], pa, vbh);
                mma_bf16(o[j], pa, vbl);
                mma_bf16(o[j], pb, vbh);
            }
        }
    }

    l0 += __shfl_xor_sync(0xffffffffu, l0, 1);
    l0 += __shfl_xor_sync(0xffffffffu, l0, 2);
    l1 += __shfl_xor_sync(0xffffffffu, l1, 1);
    l1 += __shfl_xor_sync(0xffffffffu, l1, 2);
    const float inv0 = 1.f / l0, inv1 = 1.f / l1;
    const int b = bh >> 3, h = bh & 7;
    float* d0 = out + ((size_t)(b * S_ + r0)) * D_ + h * HD_;
    float* d1 = out + ((size_t)(b * S_ + r1)) * D_ + h * HD_;
    #pragma unroll
    for (int j = 0; j < 8; j++) {
        const int col = 8 * j + 2 * c;
        *(float2*)(d0 + col) = make_float2(o[j][0] * inv0, o[j][1] * inv0);
        *(float2*)(d1 + col) = make_float2(o[j][2] * inv1, o[j][3] * inv1);
    }
}

// ---------------------------------------------------------------------------
extern "C" void kernel_launch(void* const* d_in, const int* in_sizes, int n_in,
                              void* d_out, int out_size)
{
    const float* x  = (const float*)d_in[0];
    const float* Wq = (const float*)d_in[1];
    const float* bq = (const float*)d_in[2];
    const float* Wk = (const float*)d_in[3];
    const float* bk = (const float*)d_in[4];
    const float* Wv = (const float*)d_in[5];
    const float* bv = (const float*)d_in[6];
    float* out = (float*)d_out;

    qkv_gemm<<<dim3(D_ / 64, BS_ / 128, 3), 256>>>(x, Wq, bq, Wk, bk, Wv, bv);

    cudaFuncSetAttribute(attn_kernel,
                         cudaFuncAttributeMaxDynamicSharedMemorySize, SMTOT);
    attn_kernel<<<dim3(S_ / BR, B_ * H_), 256, SMTOT>>>(out);
}

// round 9
// speedup vs baseline: 4.1371x; 1.0121x over previous
#include <cuda_runtime.h>
#include <cuda_bf16.h>
#include <cstdint>
#include <math.h>

#define B_  2
#define S_  4096
#define D_  512
#define H_  8
#define HD_ 64
#define BS_ (B_*S_)

// ===== bf16 hi/lo scratch (written by qkv_gemm, read by attention) =====
// qh/ql, kh/kl : [bh][s][hd]   (row-major over s; k-pairs contiguous in hd)
// vth/vtl      : [bh][hd][s]   (V transposed; PV B-frag k-pairs contiguous in s)
__device__ __nv_bfloat16 g_qh[B_*H_*S_*HD_];
__device__ __nv_bfloat16 g_ql[B_*H_*S_*HD_];
__device__ __nv_bfloat16 g_kh[B_*H_*S_*HD_];
__device__ __nv_bfloat16 g_kl[B_*H_*S_*HD_];
__device__ __nv_bfloat16 g_vth[B_*H_*HD_*S_];
__device__ __nv_bfloat16 g_vtl[B_*H_*HD_*S_];

__device__ __forceinline__ float ex2(float x) {
    float r; asm("ex2.approx.f32 %0, %1;" : "=f"(r) : "f"(x)); return r;
}
__device__ __forceinline__ uint32_t smem_u32(const void* p) {
    uint32_t a;
    asm("{ .reg .u64 t; cvta.to.shared.u64 t, %1; cvt.u32.u64 %0, t; }"
        : "=r"(a) : "l"(p));
    return a;
}
// cp.async 16B (baseline sm_80 ISA)
__device__ __forceinline__ void cp16(uint32_t s, const void* g) {
    asm volatile("cp.async.cg.shared.global [%0], [%1], 16;"
                 :: "r"(s), "l"(g) : "memory");
}
#define CP_COMMIT() asm volatile("cp.async.commit_group;" ::: "memory")
#define CP_WAIT1()  asm volatile("cp.async.wait_group 1;" ::: "memory")

// m16n8k16 row.col bf16 MMA, fp32 accumulate (baseline ISA, sm_80+).
__device__ __forceinline__ void mma_bf16(float* d, const uint32_t* a,
                                         const uint32_t* b) {
    asm volatile(
        "mma.sync.aligned.m16n8k16.row.col.f32.bf16.bf16.f32 "
        "{%0,%1,%2,%3}, {%4,%5,%6,%7}, {%8,%9}, {%0,%1,%2,%3};"
        : "+f"(d[0]), "+f"(d[1]), "+f"(d[2]), "+f"(d[3])
        : "r"(a[0]), "r"(a[1]), "r"(a[2]), "r"(a[3]), "r"(b[0]), "r"(b[1]));
}

__device__ __forceinline__ uint32_t packbf(float a, float b) {
    __nv_bfloat162 t = __halves2bfloat162(__float2bfloat16(a),
                                          __float2bfloat16(b));
    return *reinterpret_cast<uint32_t*>(&t);
}
// split (x, y) into hi/lo bf16 pair-packed words
__device__ __forceinline__ void split2(float x, float y, uint32_t& hi, uint32_t& lo) {
    __nv_bfloat16 hx = __float2bfloat16(x);
    __nv_bfloat16 hy = __float2bfloat16(y);
    __nv_bfloat162 th = __halves2bfloat162(hx, hy);
    hi = *reinterpret_cast<uint32_t*>(&th);
    lo = packbf(x - __bfloat162float(hx), y - __bfloat162float(hy));
}

// ---------------------------------------------------------------------------
// Fused QKV projection on mma.sync bf16 hi/lo (3-term: XhWh + XhWl + XlWh).
// Unchanged from R8 win (~122 us).
// ---------------------------------------------------------------------------
#define GP 80
#define GXH 0
#define GXL (GXH + 128*GP)
#define GWH (GXL + 128*GP)
#define GWL (GWH + 64*GP)
#define GSM (GWL + 64*GP)

__global__ void __launch_bounds__(256) qkv_gemm(
    const float* __restrict__ x,
    const float* __restrict__ Wq, const float* __restrict__ bq,
    const float* __restrict__ Wk, const float* __restrict__ bk,
    const float* __restrict__ Wv, const float* __restrict__ bv)
{
    __shared__ uint8_t sm[GSM];

    const int z = blockIdx.z;
    const float* W    = (z == 0) ? Wq : ((z == 1) ? Wk : Wv);
    const float* bias = (z == 0) ? bq : ((z == 1) ? bk : bv);

    const int bm = blockIdx.y * 128;
    const int bn = blockIdx.x * 64;
    const int tid  = threadIdx.x;
    const int wid  = tid >> 5;
    const int lane = tid & 31;
    const int g    = lane >> 2;
    const int c    = lane & 3;

    const int lr = tid >> 3;
    const int lc = (tid & 7) * 4;

    float4 xr[4], wr[2];

    float acc[8][4];
    #pragma unroll
    for (int j = 0; j < 8; j++) { acc[j][0]=acc[j][1]=acc[j][2]=acc[j][3]=0.f; }

    #pragma unroll
    for (int n = 0; n < 4; n++)
        xr[n] = *(const float4*)(x + (size_t)(bm + lr + 32*n) * D_ + lc);
    #pragma unroll
    for (int n = 0; n < 2; n++)
        wr[n] = *(const float4*)(W + (size_t)(bn + lr + 32*n) * D_ + lc);

    for (int k0 = 0; k0 < D_; k0 += 32) {
        __syncthreads();
        #pragma unroll
        for (int n = 0; n < 4; n++) {
            uint32_t h0, l0, h1, l1;
            split2(xr[n].x, xr[n].y, h0, l0);
            split2(xr[n].z, xr[n].w, h1, l1);
            uint32_t off = (uint32_t)(lr + 32*n) * GP + (uint32_t)lc * 2;
            *(uint32_t*)(sm + GXH + off)     = h0;
            *(uint32_t*)(sm + GXH + off + 4) = h1;
            *(uint32_t*)(sm + GXL + off)     = l0;
            *(uint32_t*)(sm + GXL + off + 4) = l1;
        }
        #pragma unroll
        for (int n = 0; n < 2; n++) {
            uint32_t h0, l0, h1, l1;
            split2(wr[n].x, wr[n].y, h0, l0);
            split2(wr[n].z, wr[n].w, h1, l1);
            uint32_t off = (uint32_t)(lr + 32*n) * GP + (uint32_t)lc * 2;
            *(uint32_t*)(sm + GWH + off)     = h0;
            *(uint32_t*)(sm + GWH + off + 4) = h1;
            *(uint32_t*)(sm + GWL + off)     = l0;
            *(uint32_t*)(sm + GWL + off + 4) = l1;
        }
        __syncthreads();

        if (k0 + 32 < D_) {
            #pragma unroll
            for (int n = 0; n < 4; n++)
                xr[n] = *(const float4*)(x + (size_t)(bm + lr + 32*n) * D_ +
                                         k0 + 32 + lc);
            #pragma unroll
            for (int n = 0; n < 2; n++)
                wr[n] = *(const float4*)(W + (size_t)(bn + lr + 32*n) * D_ +
                                         k0 + 32 + lc);
        }

        #pragma unroll
        for (int ks = 0; ks < 2; ks++) {
            const uint32_t a0 = (uint32_t)(wid * 16 + g)     * GP + ks * 32 + c * 4;
            const uint32_t a1 = (uint32_t)(wid * 16 + g + 8) * GP + ks * 32 + c * 4;
            uint32_t ah[4], al[4];
            ah[0] = *(const uint32_t*)(sm + GXH + a0);
            ah[1] = *(const uint32_t*)(sm + GXH + a1);
            ah[2] = *(const uint32_t*)(sm + GXH + a0 + 16);
            ah[3] = *(const uint32_t*)(sm + GXH + a1 + 16);
            al[0] = *(const uint32_t*)(sm + GXL + a0);
            al[1] = *(const uint32_t*)(sm + GXL + a1);
            al[2] = *(const uint32_t*)(sm + GXL + a0 + 16);
            al[3] = *(const uint32_t*)(sm + GXL + a1 + 16);
            #pragma unroll
            for (int j = 0; j < 8; j++) {
                const uint32_t bo = (uint32_t)(8 * j + g) * GP + ks * 32 + c * 4;
                uint32_t bh2[2], bl2[2];
                bh2[0] = *(const uint32_t*)(sm + GWH + bo);
                bh2[1] = *(const uint32_t*)(sm + GWH + bo + 16);
                bl2[0] = *(const uint32_t*)(sm + GWL + bo);
                bl2[1] = *(const uint32_t*)(sm + GWL + bo + 16);
                mma_bf16(acc[j], ah, bh2);
                mma_bf16(acc[j], ah, bl2);
                mma_bf16(acc[j], al, bh2);
            }
        }
    }

    const int r0 = bm + wid * 16 + g;
    const int b  = r0 >> 12;
    const int s0 = r0 & 4095;
    const float QS = 0.044194173824159216f * 1.4426950408889634f;

    if (z < 2) {
        __nv_bfloat16* dh = (z == 0) ? g_qh : g_kh;
        __nv_bfloat16* dl = (z == 0) ? g_ql : g_kl;
        const float sc = (z == 0) ? QS : 1.0f;
        #pragma unroll
        for (int j = 0; j < 8; j++) {
            const int n  = bn + 8 * j + 2 * c;
            const int h  = n >> 6;
            const int hd = n & 63;
            float2 bv2 = *(const float2*)&bias[n];
            size_t base0 = (((size_t)(b * H_ + h)) * S_ + s0)     * HD_ + hd;
            size_t base1 = (((size_t)(b * H_ + h)) * S_ + s0 + 8) * HD_ + hd;
            uint32_t hi, lo;
            split2((acc[j][0] + bv2.x) * sc, (acc[j][1] + bv2.y) * sc, hi, lo);
            *(uint32_t*)&dh[base0] = hi;  *(uint32_t*)&dl[base0] = lo;
            split2((acc[j][2] + bv2.x) * sc, (acc[j][3] + bv2.y) * sc, hi, lo);
            *(uint32_t*)&dh[base1] = hi;  *(uint32_t*)&dl[base1] = lo;
        }
    } else {
        #pragma unroll
        for (int j = 0; j < 8; j++) {
            const int n  = bn + 8 * j + 2 * c;
            const int h  = n >> 6;
            const int hd = n & 63;
            float2 bv2 = *(const float2*)&bias[n];
            size_t c0 = (((size_t)(b * H_ + h)) * HD_ + hd)     * S_;
            size_t c1 = (((size_t)(b * H_ + h)) * HD_ + hd + 1) * S_;
            float v00 = acc[j][0] + bv2.x, v01 = acc[j][1] + bv2.y;
            float v10 = acc[j][2] + bv2.x, v11 = acc[j][3] + bv2.y;
            __nv_bfloat16 h00 = __float2bfloat16(v00);
            __nv_bfloat16 h01 = __float2bfloat16(v01);
            __nv_bfloat16 h10 = __float2bfloat16(v10);
            __nv_bfloat16 h11 = __float2bfloat16(v11);
            g_vth[c0 + s0]     = h00;
            g_vth[c1 + s0]     = h01;
            g_vth[c0 + s0 + 8] = h10;
            g_vth[c1 + s0 + 8] = h11;
            g_vtl[c0 + s0]     = __float2bfloat16(v00 - __bfloat162float(h00));
            g_vtl[c1 + s0]     = __float2bfloat16(v01 - __bfloat162float(h01));
            g_vtl[c0 + s0 + 8] = __float2bfloat16(v10 - __bfloat162float(h10));
            g_vtl[c1 + s0 + 8] = __float2bfloat16(v11 - __bfloat162float(h11));
        }
    }
}

// ---------------------------------------------------------------------------
// mma.sync causal flash attention with cp.async double-buffered K/V tiles.
// 256 thr / 8 warps. Br=128, Bc=64. 3-term hi/lo bf16; P in registers.
// Smem: Q (hi/lo) + 2 stages of {Kh,Kl,Vh,Vl}. Stage kt+2 prefetch overlaps
// tile kt+1 compute.
// ---------------------------------------------------------------------------
#define BR 128
#define BC 64
#define RP 144

#define SQH 0
#define SQL (SQH + BR*RP)            // 18432
#define SKV (SQL + BR*RP)            // 36864 : stage 0 base
#define SKH_O 0
#define SKL_O (BC*RP)                // 9216
#define SVH_O (2*BC*RP)              // 18432
#define SVL_O (3*BC*RP)              // 27648
#define SSTG  (4*BC*RP)              // 36864 per stage
#define SMTOT (SKV + 2*SSTG)         // 110592

__global__ void __launch_bounds__(256) attn_kernel(float* __restrict__ out)
{
    extern __shared__ uint8_t sm[];
    const uint32_t sb = smem_u32(sm);
    const int tid  = threadIdx.x;
    const int wid  = tid >> 5;
    const int lane = tid & 31;
    const int g    = lane >> 2;
    const int c    = lane & 3;

    const int qt = 31 - (int)blockIdx.x;
    const int bh = blockIdx.y;
    const int q0 = qt * BR;
    const int nkt = 2 * qt + 2;

    // prefetch helper: tile kt2 -> stage
    auto prefetch = [&](int kt2) {
        const int k0 = kt2 * BC;
        const uint32_t stg = SKV + (uint32_t)(kt2 & 1) * SSTG;
        const __nv_bfloat16* kh = g_kh + ((size_t)bh * S_ + k0) * HD_;
        const __nv_bfloat16* kl = g_kl + ((size_t)bh * S_ + k0) * HD_;
        const __nv_bfloat16* vh = g_vth + (size_t)bh * HD_ * S_ + k0;
        const __nv_bfloat16* vl = g_vtl + (size_t)bh * HD_ * S_ + k0;
        for (int i = tid; i < BC * 8; i += 256) {
            int r = i >> 3, c8 = i & 7;
            uint32_t off = (uint32_t)(r * RP + c8 * 16);
            cp16(sb + stg + SKH_O + off, kh + r * HD_ + c8 * 8);
            cp16(sb + stg + SKL_O + off, kl + r * HD_ + c8 * 8);
            cp16(sb + stg + SVH_O + off, vh + (size_t)r * S_ + c8 * 8);
            cp16(sb + stg + SVL_O + off, vl + (size_t)r * S_ + c8 * 8);
        }
    };

    // kick off tiles 0 and 1 (nkt >= 2 always)
    prefetch(0); CP_COMMIT();
    prefetch(1); CP_COMMIT();

    // Q tile (hi/lo) via regular loads, overlapped with the cp.asyncs above
    {
        const __nv_bfloat16* qh = g_qh + ((size_t)bh * S_ + q0) * HD_;
        const __nv_bfloat16* ql = g_ql + ((size_t)bh * S_ + q0) * HD_;
        for (int i = tid; i < BR * 8; i += 256) {
            int r = i >> 3, c8 = i & 7;
            *(uint4*)(sm + SQH + r * RP + c8 * 16) =
                *(const uint4*)(qh + r * HD_ + c8 * 8);
            *(uint4*)(sm + SQL + r * RP + c8 * 16) =
                *(const uint4*)(ql + r * HD_ + c8 * 8);
        }
    }

    float o[8][4];
    #pragma unroll
    for (int j = 0; j < 8; j++) { o[j][0] = o[j][1] = o[j][2] = o[j][3] = 0.f; }
    float m0 = -INFINITY, m1 = -INFINITY, l0 = 0.f, l1 = 0.f;

    const int r0 = q0 + wid * 16 + g;
    const int r1 = r0 + 8;

    for (int kt = 0; kt < nkt; kt++) {
        const int k0 = kt * BC;
        const uint32_t stg = SKV + (uint32_t)(kt & 1) * SSTG;

        CP_WAIT1();            // tile kt landed (kt+1 may still be in flight)
        __syncthreads();       // visibility + all warps done with this stage

        float s[8][4];
        #pragma unroll
        for (int j = 0; j < 8; j++) { s[j][0] = s[j][1] = s[j][2] = s[j][3] = 0.f; }

        #pragma unroll
        for (int ks = 0; ks < 4; ks++) {
            const uint32_t arow0 = (wid * 16 + g)     * RP + ks * 32 + c * 4;
            const uint32_t arow1 = (wid * 16 + g + 8) * RP + ks * 32 + c * 4;
            uint32_t ah[4], al[4];
            ah[0] = *(const uint32_t*)(sm + SQH + arow0);
            ah[1] = *(const uint32_t*)(sm + SQH + arow1);
            ah[2] = *(const uint32_t*)(sm + SQH + arow0 + 16);
            ah[3] = *(const uint32_t*)(sm + SQH + arow1 + 16);
            al[0] = *(const uint32_t*)(sm + SQL + arow0);
            al[1] = *(const uint32_t*)(sm + SQL + arow1);
            al[2] = *(const uint32_t*)(sm + SQL + arow0 + 16);
            al[3] = *(const uint32_t*)(sm + SQL + arow1 + 16);
            #pragma unroll
            for (int j = 0; j < 8; j++) {
                const uint32_t koff = stg + SKH_O + (8 * j + g) * RP + ks * 32 + c * 4;
                const uint32_t loff = stg + SKL_O + (8 * j + g) * RP + ks * 32 + c * 4;
                uint32_t bhf[2], blf[2];
                bhf[0] = *(const uint32_t*)(sm + koff);
                bhf[1] = *(const uint32_t*)(sm + koff + 16);
                blf[0] = *(const uint32_t*)(sm + loff);
                blf[1] = *(const uint32_t*)(sm + loff + 16);
                mma_bf16(s[j], ah, bhf);
                mma_bf16(s[j], ah, blf);
                mma_bf16(s[j], al, bhf);
            }
        }

        if (kt >= 2 * qt) {
            #pragma unroll
            for (int j = 0; j < 8; j++) {
                int col = k0 + 8 * j + 2 * c;
                if (col     > r0) s[j][0] = -INFINITY;
                if (col + 1 > r0) s[j][1] = -INFINITY;
                if (col     > r1) s[j][2] = -INFINITY;
                if (col + 1 > r1) s[j][3] = -INFINITY;
            }
        }

        float mx0 = -INFINITY, mx1 = -INFINITY;
        #pragma unroll
        for (int j = 0; j < 8; j++) {
            mx0 = fmaxf(mx0, fmaxf(s[j][0], s[j][1]));
            mx1 = fmaxf(mx1, fmaxf(s[j][2], s[j][3]));
        }
        mx0 = fmaxf(mx0, __shfl_xor_sync(0xffffffffu, mx0, 1));
        mx0 = fmaxf(mx0, __shfl_xor_sync(0xffffffffu, mx0, 2));
        mx1 = fmaxf(mx1, __shfl_xor_sync(0xffffffffu, mx1, 1));
        mx1 = fmaxf(mx1, __shfl_xor_sync(0xffffffffu, mx1, 2));
        const float mn0 = fmaxf(m0, mx0), mn1 = fmaxf(m1, mx1);
        const float cr0 = ex2(m0 - mn0),  cr1 = ex2(m1 - mn1);
        m0 = mn0; m1 = mn1;

        uint32_t phr0[8], phr1[8], plr0[8], plr1[8];
        float ls0 = 0.f, ls1 = 0.f;
        #pragma unroll
        for (int j = 0; j < 8; j++) {
            float p00 = ex2(s[j][0] - mn0), p01 = ex2(s[j][1] - mn0);
            float p10 = ex2(s[j][2] - mn1), p11 = ex2(s[j][3] - mn1);
            ls0 += p00 + p01; ls1 += p10 + p11;
            __nv_bfloat16 h00 = __float2bfloat16(p00);
            __nv_bfloat16 h01 = __float2bfloat16(p01);
            __nv_bfloat16 h10 = __float2bfloat16(p10);
            __nv_bfloat16 h11 = __float2bfloat16(p11);
            __nv_bfloat162 t0 = __halves2bfloat162(h00, h01);
            __nv_bfloat162 t1 = __halves2bfloat162(h10, h11);
            phr0[j] = *reinterpret_cast<uint32_t*>(&t0);
            phr1[j] = *reinterpret_cast<uint32_t*>(&t1);
            plr0[j] = packbf(p00 - __bfloat162float(h00),
                             p01 - __bfloat162float(h01));
            plr1[j] = packbf(p10 - __bfloat162float(h10),
                             p11 - __bfloat162float(h11));
        }
        l0 = l0 * cr0 + ls0;
        l1 = l1 * cr1 + ls1;
        #pragma unroll
        for (int j = 0; j < 8; j++) {
            o[j][0] *= cr0; o[j][1] *= cr0;
            o[j][2] *= cr1; o[j][3] *= cr1;
        }

        #pragma unroll
        for (int ks = 0; ks < 4; ks++) {
            uint32_t pa[4] = { phr0[2*ks], phr1[2*ks], phr0[2*ks+1], phr1[2*ks+1] };
            uint32_t pb[4] = { plr0[2*ks], plr1[2*ks], plr0[2*ks+1], plr1[2*ks+1] };
            #pragma unroll
            for (int j = 0; j < 8; j++) {
                const uint32_t vhof = stg + SVH_O + (8 * j + g) * RP + ks * 32 + c * 4;
                const uint32_t vlof = stg + SVL_O + (8 * j + g) * RP + ks * 32 + c * 4;
                uint32_t vbh[2], vbl[2];
                vbh[0] = *(const uint32_t*)(sm + vhof);
                vbh[1] = *(const uint32_t*)(sm + vhof + 16);
                vbl[0] = *(const uint32_t*)(sm + vlof);
                vbl[1] = *(const uint32_t*)(sm + vlof + 16);
                mma_bf16(o[j], pa, vbh);
                mma_bf16(o[j], pa, vbl);
                mma_bf16(o[j], pb, vbh);
            }
        }

        __syncthreads();       // all warps done reading stage (kt&1)
        if (kt + 2 < nkt) prefetch(kt + 2);
        CP_COMMIT();           // commit (possibly empty) to keep group count uniform
    }

    l0 += __shfl_xor_sync(0xffffffffu, l0, 1);
    l0 += __shfl_xor_sync(0xffffffffu, l0, 2);
    l1 += __shfl_xor_sync(0xffffffffu, l1, 1);
    l1 += __shfl_xor_sync(0xffffffffu, l1, 2);
    const float inv0 = 1.f / l0, inv1 = 1.f / l1;
    const int b = bh >> 3, h = bh & 7;
    float* d0 = out + ((size_t)(b * S_ + r0)) * D_ + h * HD_;
    float* d1 = out + ((size_t)(b * S_ + r1)) * D_ + h * HD_;
    #pragma unroll
    for (int j = 0; j < 8; j++) {
        const int col = 8 * j + 2 * c;
        *(float2*)(d0 + col) = make_float2(o[j][0] * inv0, o[j][1] * inv0);
        *(float2*)(d1 + col) = make_float2(o[j][2] * inv1, o[j][3] * inv1);
    }
}

// ---------------------------------------------------------------------------
extern "C" void kernel_launch(void* const* d_in, const int* in_sizes, int n_in,
                              void* d_out, int out_size)
{
    const float* x  = (const float*)d_in[0];
    const float* Wq = (const float*)d_in[1];
    const float* bq = (const float*)d_in[2];
    const float* Wk = (const float*)d_in[3];
    const float* bk = (const float*)d_in[4];
    const float* Wv = (const float*)d_in[5];
    const float* bv = (const float*)d_in[6];
    float* out = (float*)d_out;

    qkv_gemm<<<dim3(D_ / 64, BS_ / 128, 3), 256>>>(x, Wq, bq, Wk, bk, Wv, bv);

    cudaFuncSetAttribute(attn_kernel,
                         cudaFuncAttributeMaxDynamicSharedMemorySize, SMTOT);
    attn_kernel<<<dim3(S_ / BR, B_ * H_), 256, SMTOT>>>(out);
}